// round 9
// baseline (speedup 1.0000x reference)
#include <cuda_runtime.h>
#include <cuda_bf16.h>
#include <math.h>
#include <stdint.h>

#define B_SZ   1024
#define C_SZ   100000
#define C_PAD  100096          /* 391 * 256 */
#define D_SZ   256
#define EPSV   1e-12f
#define SCALAR 30.0f
#define MOM    0.5f

// out layout: predicts | targets(as float) | new_weight
#define OUT_PRED 0
#define OUT_TGT  (B_SZ * C_SZ)
#define OUT_W    (B_SZ * C_SZ + B_SZ)

// ---------------- scratch (static device globals; no allocs) ----------------
__device__ float g_xnorm[B_SZ * D_SZ];
__device__ float g_winv[C_PAD];
__device__ __align__(16) __nv_bfloat16 g_xa_hi[B_SZ * D_SZ];
__device__ __align__(16) __nv_bfloat16 g_xa_lo[B_SZ * D_SZ];
__device__ __align__(16) __nv_bfloat16 g_w_hi[(size_t)C_PAD * D_SZ];
__device__ __align__(16) __nv_bfloat16 g_w_lo[(size_t)C_PAD * D_SZ];

// ---------------- PTX helpers (portable: sm_80+ instructions only) ----------
__device__ __forceinline__ uint32_t smem_u32(const void* p) {
    uint32_t a;
    asm("{ .reg .u64 t; cvta.to.shared.u64 t, %1; cvt.u32.u64 %0, t; }" : "=r"(a) : "l"(p));
    return a;
}
__device__ __forceinline__ void cpa16(uint32_t dst, const void* src) {
    asm volatile("cp.async.cg.shared.global [%0], [%1], 16;"
        :: "r"(dst), "l"((unsigned long long)__cvta_generic_to_global(src)) : "memory");
}
#define CP_COMMIT() asm volatile("cp.async.commit_group;" ::: "memory")
#define CP_WAIT(n)  asm volatile("cp.async.wait_group %0;" :: "n"(n) : "memory")

__device__ __forceinline__ void ldsm_x4(uint32_t* r, uint32_t addr) {
    asm volatile("ldmatrix.sync.aligned.m8n8.x4.shared.b16 {%0,%1,%2,%3}, [%4];"
        : "=r"(r[0]), "=r"(r[1]), "=r"(r[2]), "=r"(r[3]) : "r"(addr));
}
__device__ __forceinline__ void mma16816(float* c, const uint32_t* a, const uint32_t* b) {
    asm volatile("mma.sync.aligned.m16n8k16.row.col.f32.bf16.bf16.f32 "
        "{%0,%1,%2,%3}, {%4,%5,%6,%7}, {%8,%9}, {%0,%1,%2,%3};"
        : "+f"(c[0]), "+f"(c[1]), "+f"(c[2]), "+f"(c[3])
        : "r"(a[0]), "r"(a[1]), "r"(a[2]), "r"(a[3]), "r"(b[0]), "r"(b[1]));
}

// ---------------------------------------------------------------------------
// 1) normalize inputs + emit bf16 hi/lo split
// ---------------------------------------------------------------------------
__global__ void normalize_x_kernel(const float* __restrict__ x) {
    int b = blockIdx.x;
    int t = threadIdx.x;
    float v = x[b * D_SZ + t];
    float ss = v * v;
    __shared__ float sm[8];
    for (int o = 16; o; o >>= 1) ss += __shfl_xor_sync(0xFFFFFFFFu, ss, o);
    int w = t >> 5, l = t & 31;
    if (l == 0) sm[w] = ss;
    __syncthreads();
    if (w == 0) {
        float s = (l < 8) ? sm[l] : 0.0f;
        for (int o = 4; o; o >>= 1) s += __shfl_xor_sync(0xFFFFFFFFu, s, o);
        if (l == 0) sm[0] = s;
    }
    __syncthreads();
    float nrm = sqrtf(sm[0]);
    float xn = v / fmaxf(nrm, EPSV);
    g_xnorm[b * D_SZ + t] = xn;
    __nv_bfloat16 h = __float2bfloat16(xn);
    __nv_bfloat16 lo = __float2bfloat16(xn - __bfloat162float(h));
    g_xa_hi[b * D_SZ + t] = h;
    g_xa_lo[b * D_SZ + t] = lo;
}

// ---------------------------------------------------------------------------
// 2) per-class scale winv[c] = SCALAR / max(||w_c||, eps); padded -> 0
// ---------------------------------------------------------------------------
__global__ void winv_kernel(const float* __restrict__ w) {
    int warp = (blockIdx.x * blockDim.x + threadIdx.x) >> 5;
    int lane = threadIdx.x & 31;
    if (warp >= C_PAD) return;
    if (warp >= C_SZ) { if (lane == 0) g_winv[warp] = 0.0f; return; }
    const float* row = w + (size_t)warp * D_SZ + lane * 8;
    float4 a = *(const float4*)(row);
    float4 b = *(const float4*)(row + 4);
    float ss = a.x*a.x + a.y*a.y + a.z*a.z + a.w*a.w
             + b.x*b.x + b.y*b.y + b.z*b.z + b.w*b.w;
    for (int o = 16; o; o >>= 1) ss += __shfl_xor_sync(0xFFFFFFFFu, ss, o);
    if (lane == 0) g_winv[warp] = SCALAR / fmaxf(sqrtf(ss), EPSV);
}

// ---------------------------------------------------------------------------
// 3) weight -> bf16 hi/lo split (padded rows zeroed)
// ---------------------------------------------------------------------------
__global__ void convert_w_kernel(const float* __restrict__ w) {
    size_t i = (size_t)blockIdx.x * blockDim.x + threadIdx.x; // 8 elems each
    size_t n = (size_t)C_PAD * D_SZ / 8;
    if (i >= n) return;
    size_t e0 = i * 8;
    __nv_bfloat16 hs[8], ls[8];
    if (e0 < (size_t)C_SZ * D_SZ) {
        float4 a = ((const float4*)(w + e0))[0];
        float4 b = ((const float4*)(w + e0))[1];
        float v[8] = {a.x, a.y, a.z, a.w, b.x, b.y, b.z, b.w};
#pragma unroll
        for (int k = 0; k < 8; ++k) {
            __nv_bfloat16 h = __float2bfloat16(v[k]);
            hs[k] = h;
            ls[k] = __float2bfloat16(v[k] - __bfloat162float(h));
        }
    } else {
#pragma unroll
        for (int k = 0; k < 8; ++k) { hs[k] = __float2bfloat16(0.f); ls[k] = hs[k]; }
    }
    *(uint4*)(g_w_hi + e0) = *(uint4*)hs;
    *(uint4*)(g_w_lo + e0) = *(uint4*)ls;
}

// ---------------------------------------------------------------------------
// 4) copy raw weight into new_weight output region
// ---------------------------------------------------------------------------
__global__ void copy_w_kernel(const float* __restrict__ w, float* __restrict__ dst) {
    size_t i = (size_t)blockIdx.x * blockDim.x + threadIdx.x;
    size_t n4 = (size_t)C_SZ * D_SZ / 4;
    if (i < n4) ((float4*)dst)[i] = ((const float4*)w)[i];
}

// ---------------------------------------------------------------------------
// 5) targets -> float
// ---------------------------------------------------------------------------
__global__ void targets_out_kernel(const int* __restrict__ tgt, float* __restrict__ dst) {
    int i = blockIdx.x * blockDim.x + threadIdx.x;
    if (i < B_SZ) dst[i] = (float)tgt[i];
}

// ---------------------------------------------------------------------------
// 6) sequential momentum update (exact batch order, duplicate-safe)
// ---------------------------------------------------------------------------
__global__ void seq_update_kernel(const int* __restrict__ tgt, float* __restrict__ wout) {
    int i = blockIdx.x;
    int t = threadIdx.x;
    int cls = tgt[i];
    __shared__ int first;
    __shared__ float sm[9];
    if (t == 0) first = 1;
    __syncthreads();
    for (int j = t; j < i; j += 256)
        if (tgt[j] == cls) first = 0;
    __syncthreads();
    if (!first) return;
    float v = wout[(size_t)cls * D_SZ + t];
    for (int j = i; j < B_SZ; ++j) {
        if (tgt[j] != cls) continue;
        v = MOM * v + (1.0f - MOM) * g_xnorm[j * D_SZ + t];
        float ss = v * v;
        for (int o = 16; o; o >>= 1) ss += __shfl_xor_sync(0xFFFFFFFFu, ss, o);
        int w = t >> 5, l = t & 31;
        if (l == 0) sm[w] = ss;
        __syncthreads();
        if (t == 0) {
            float s = 0.0f;
            for (int k = 0; k < 8; ++k) s += sm[k];
            sm[8] = s;
        }
        __syncthreads();
        v = v / fmaxf(sqrtf(sm[8]), EPSV);
        __syncthreads();
    }
    wout[(size_t)cls * D_SZ + t] = v;
}

// ---------------------------------------------------------------------------
// 7) mma.sync bf16 hi/lo GEMM, CTA tile 128(M) x 256(N), 8 warps of 64x64.
//    k-chunk 32, 3-stage cp.async pipeline.
// ---------------------------------------------------------------------------
#define PITCH       80                        /* bytes per smem row (32 bf16 + pad) */
#define A_TILE      (128 * PITCH)             /* 10240 */
#define B_TILE      (256 * PITCH)             /* 20480 */
#define OFF_AHI     0
#define OFF_ALO     A_TILE
#define OFF_BHI     (2 * A_TILE)
#define OFF_BLO     (2 * A_TILE + B_TILE)
#define STAGE_BYTES (2 * A_TILE + 2 * B_TILE) /* 61440 */
#define SMEM_GEMM   (3 * STAGE_BYTES)         /* 184320 */

__device__ __forceinline__ void load_chunk(uint32_t stage, int kc, int b0, int c0, int tid) {
    // A tiles: 128 rows x 4 segs (16B each), hi+lo -> 2 segs per thread each
#pragma unroll
    for (int i = 0; i < 2; ++i) {
        int s = tid * 2 + i;
        int row = s >> 2, cs = s & 3;
        uint32_t so = (uint32_t)(row * PITCH + cs * 16);
        size_t g = (size_t)(b0 + row) * D_SZ + kc * 32 + cs * 8;
        cpa16(stage + OFF_AHI + so, g_xa_hi + g);
        cpa16(stage + OFF_ALO + so, g_xa_lo + g);
    }
    // B tiles: 256 rows x 4 segs, hi+lo -> 4 segs per thread each
#pragma unroll
    for (int i = 0; i < 4; ++i) {
        int s = tid * 4 + i;
        int row = s >> 2, cs = s & 3;
        uint32_t so = (uint32_t)(row * PITCH + cs * 16);
        size_t g = (size_t)(c0 + row) * D_SZ + kc * 32 + cs * 8;
        cpa16(stage + OFF_BHI + so, g_w_hi + g);
        cpa16(stage + OFF_BLO + so, g_w_lo + g);
    }
    CP_COMMIT();
}

__global__ void __launch_bounds__(256, 1) gemm_mma_kernel(float* __restrict__ out) {
    extern __shared__ char smem[];
    uint32_t sb = smem_u32(smem);
    __shared__ float sw_winv[256];

    int tid = threadIdx.x, lane = tid & 31, warp = tid >> 5;
    int warp_m = warp >> 2;        // 0..1  (64 rows)
    int warp_n = warp & 3;         // 0..3  (64 cols)
    int b0 = blockIdx.x * 128;
    int c0 = blockIdx.y * 256;

    sw_winv[tid] = g_winv[c0 + tid];

    float acc[4][8][4];
#pragma unroll
    for (int mi = 0; mi < 4; ++mi)
#pragma unroll
        for (int ni = 0; ni < 8; ++ni)
#pragma unroll
            for (int q = 0; q < 4; ++q) acc[mi][ni][q] = 0.0f;

    // lane-derived ldmatrix row offsets
    int arow = (lane & 7) + ((lane >> 3) & 1) * 8;
    int aseg = lane >> 4;                                   // 0/1 -> +16B
    uint32_t a_off = (uint32_t)((warp_m * 64 + arow) * PITCH + aseg * 16);
    int brow = (lane & 7) + (lane >> 4) * 8;
    int bseg = (lane >> 3) & 1;
    uint32_t b_off = (uint32_t)((warp_n * 64 + brow) * PITCH + bseg * 16);

    load_chunk(sb + 0 * STAGE_BYTES, 0, b0, c0, tid);
    load_chunk(sb + 1 * STAGE_BYTES, 1, b0, c0, tid);
    load_chunk(sb + 2 * STAGE_BYTES, 2, b0, c0, tid);

#pragma unroll
    for (int kc = 0; kc < 8; ++kc) {
        if (kc <= 5) { CP_WAIT(2); } else if (kc == 6) { CP_WAIT(1); } else { CP_WAIT(0); }
        __syncthreads();
        uint32_t st = sb + (uint32_t)(kc % 3) * STAGE_BYTES;

#pragma unroll
        for (int kk = 0; kk < 2; ++kk) {
            uint32_t koff = (uint32_t)(kk * 32);
            uint32_t af[4][4], bh[4][4], bl[4][4];
#pragma unroll
            for (int mi = 0; mi < 4; ++mi)
                ldsm_x4(af[mi], st + OFF_AHI + a_off + mi * (16 * PITCH) + koff);
#pragma unroll
            for (int n2 = 0; n2 < 4; ++n2)
                ldsm_x4(bh[n2], st + OFF_BHI + b_off + n2 * (16 * PITCH) + koff);
#pragma unroll
            for (int n2 = 0; n2 < 4; ++n2)
                ldsm_x4(bl[n2], st + OFF_BLO + b_off + n2 * (16 * PITCH) + koff);

            // pass 0: A_hi x B_hi,  pass 1: A_hi x B_lo
#pragma unroll
            for (int mi = 0; mi < 4; ++mi)
#pragma unroll
                for (int ni = 0; ni < 8; ++ni) {
                    uint32_t bhp[2] = { bh[ni >> 1][(ni & 1) * 2], bh[ni >> 1][(ni & 1) * 2 + 1] };
                    mma16816(acc[mi][ni], af[mi], bhp);
                    uint32_t blp[2] = { bl[ni >> 1][(ni & 1) * 2], bl[ni >> 1][(ni & 1) * 2 + 1] };
                    mma16816(acc[mi][ni], af[mi], blp);
                }

            // pass 2: A_lo x B_hi
#pragma unroll
            for (int mi = 0; mi < 4; ++mi)
                ldsm_x4(af[mi], st + OFF_ALO + a_off + mi * (16 * PITCH) + koff);
#pragma unroll
            for (int mi = 0; mi < 4; ++mi)
#pragma unroll
                for (int ni = 0; ni < 8; ++ni) {
                    uint32_t bhp[2] = { bh[ni >> 1][(ni & 1) * 2], bh[ni >> 1][(ni & 1) * 2 + 1] };
                    mma16816(acc[mi][ni], af[mi], bhp);
                }
        }
        __syncthreads();
        if (kc < 5) load_chunk(st, kc + 3, b0, c0, tid);
    }

    // epilogue: scale by winv, write predicts (guard C_SZ edge; stores 2-col aligned)
    int rbase = warp_m * 64 + (lane >> 2);
    int ncol2 = 2 * (lane & 3);
#pragma unroll
    for (int mi = 0; mi < 4; ++mi) {
#pragma unroll
        for (int ni = 0; ni < 8; ++ni) {
            int n_local = warp_n * 64 + ni * 8 + ncol2;
            int n_glob  = c0 + n_local;
            if (n_glob >= C_SZ) continue;
            float w0 = sw_winv[n_local], w1 = sw_winv[n_local + 1];
            int m0 = b0 + rbase + mi * 16;
            float2 v0 = make_float2(acc[mi][ni][0] * w0, acc[mi][ni][1] * w1);
            float2 v1 = make_float2(acc[mi][ni][2] * w0, acc[mi][ni][3] * w1);
            *(float2*)(out + (size_t)m0 * C_SZ + n_glob)       = v0;
            *(float2*)(out + (size_t)(m0 + 8) * C_SZ + n_glob) = v1;
        }
    }
}

// ---------------------------------------------------------------------------
extern "C" void kernel_launch(void* const* d_in, const int* in_sizes, int n_in,
                              void* d_out, int out_size) {
    const float* x   = (const float*)d_in[0];
    const int*   tgt = (const int*)d_in[1];
    const float* w   = (const float*)d_in[2];
    float* out = (float*)d_out;

    static bool attr_set = false;
    if (!attr_set) {
        cudaFuncSetAttribute(gemm_mma_kernel, cudaFuncAttributeMaxDynamicSharedMemorySize, SMEM_GEMM);
        attr_set = true;
    }

    normalize_x_kernel<<<B_SZ, 256>>>(x);
    winv_kernel<<<(C_PAD * 32 + 255) / 256, 256>>>(w);
    convert_w_kernel<<<(int)(((size_t)C_PAD * D_SZ / 8 + 255) / 256), 256>>>(w);
    copy_w_kernel<<<(C_SZ * D_SZ / 4 + 255) / 256, 256>>>(w, out + OUT_W);
    targets_out_kernel<<<(B_SZ + 255) / 256, 256>>>(tgt, out + OUT_TGT);
    seq_update_kernel<<<B_SZ, 256>>>(tgt, out + OUT_W);

    dim3 grid(B_SZ / 128, C_PAD / 256);   // (8, 391); x fastest -> CTAs sharing B tile run together
    gemm_mma_kernel<<<grid, 256, SMEM_GEMM>>>(out + OUT_PRED);
}

// round 12
// speedup vs baseline: 1.6504x; 1.6504x over previous
#include <cuda_runtime.h>
#include <cuda_bf16.h>
#include <cuda_fp16.h>
#include <math.h>
#include <stdint.h>

#define B_SZ   1024
#define C_SZ   100000
#define C_PAD  100096          /* 391 * 256 */
#define D_SZ   256
#define EPSV   1e-12f
#define SCALAR 30.0f
#define MOM    0.5f

// out layout: predicts | targets(as float) | new_weight
#define OUT_PRED 0
#define OUT_TGT  (B_SZ * C_SZ)
#define OUT_W    (B_SZ * C_SZ + B_SZ)

// ---------------- scratch (static device globals; no allocs) ----------------
__device__ float g_xnorm[B_SZ * D_SZ];
__device__ float g_winv[C_PAD];
__device__ __align__(16) __half g_xh[B_SZ * D_SZ];
__device__ __align__(16) __half g_w16[(size_t)C_PAD * D_SZ];

// ---------------- PTX helpers (portable: sm_80+ instructions only) ----------
__device__ __forceinline__ uint32_t smem_u32(const void* p) {
    uint32_t a;
    asm("{ .reg .u64 t; cvta.to.shared.u64 t, %1; cvt.u32.u64 %0, t; }" : "=r"(a) : "l"(p));
    return a;
}
__device__ __forceinline__ void cpa16(uint32_t dst, const void* src) {
    asm volatile("cp.async.cg.shared.global [%0], [%1], 16;"
        :: "r"(dst), "l"((unsigned long long)__cvta_generic_to_global(src)) : "memory");
}
#define CP_COMMIT() asm volatile("cp.async.commit_group;" ::: "memory")
#define CP_WAIT(n)  asm volatile("cp.async.wait_group %0;" :: "n"(n) : "memory")

__device__ __forceinline__ void ldsm_x4(uint32_t* r, uint32_t addr) {
    asm volatile("ldmatrix.sync.aligned.m8n8.x4.shared.b16 {%0,%1,%2,%3}, [%4];"
        : "=r"(r[0]), "=r"(r[1]), "=r"(r[2]), "=r"(r[3]) : "r"(addr));
}
__device__ __forceinline__ void mma16816_f16(float* c, const uint32_t* a, const uint32_t* b) {
    asm volatile("mma.sync.aligned.m16n8k16.row.col.f32.f16.f16.f32 "
        "{%0,%1,%2,%3}, {%4,%5,%6,%7}, {%8,%9}, {%0,%1,%2,%3};"
        : "+f"(c[0]), "+f"(c[1]), "+f"(c[2]), "+f"(c[3])
        : "r"(a[0]), "r"(a[1]), "r"(a[2]), "r"(a[3]), "r"(b[0]), "r"(b[1]));
}

// ---------------------------------------------------------------------------
// 1) normalize inputs (fp32 for seq_update) + emit fp16
// ---------------------------------------------------------------------------
__global__ void normalize_x_kernel(const float* __restrict__ x) {
    int b = blockIdx.x;
    int t = threadIdx.x;
    float v = x[b * D_SZ + t];
    float ss = v * v;
    __shared__ float sm[8];
    for (int o = 16; o; o >>= 1) ss += __shfl_xor_sync(0xFFFFFFFFu, ss, o);
    int w = t >> 5, l = t & 31;
    if (l == 0) sm[w] = ss;
    __syncthreads();
    if (w == 0) {
        float s = (l < 8) ? sm[l] : 0.0f;
        for (int o = 4; o; o >>= 1) s += __shfl_xor_sync(0xFFFFFFFFu, s, o);
        if (l == 0) sm[0] = s;
    }
    __syncthreads();
    float nrm = sqrtf(sm[0]);
    float xn = v / fmaxf(nrm, EPSV);
    g_xnorm[b * D_SZ + t] = xn;
    g_xh[b * D_SZ + t] = __float2half_rn(xn);
}

// ---------------------------------------------------------------------------
// 2) fused weight prep: one read of w produces
//    - fp32 copy into new_weight output region
//    - fp16 conversion for the GEMM (pad rows zeroed)
//    - winv[c] = SCALAR / max(||w_c||, eps) (pad -> 0)
// ---------------------------------------------------------------------------
__global__ void prep_w_kernel(const float* __restrict__ w, float* __restrict__ wcopy) {
    int row = blockIdx.x;
    int t = threadIdx.x;
    if (row >= C_SZ) {
        g_w16[(size_t)row * D_SZ + t] = __float2half_rn(0.0f);
        if (t == 0) g_winv[row] = 0.0f;
        return;
    }
    float v = w[(size_t)row * D_SZ + t];
    float ss = v * v;
    __shared__ float sm[8];
    for (int o = 16; o; o >>= 1) ss += __shfl_xor_sync(0xFFFFFFFFu, ss, o);
    int wi = t >> 5, l = t & 31;
    if (l == 0) sm[wi] = ss;
    __syncthreads();
    if (wi == 0) {
        float s = (l < 8) ? sm[l] : 0.0f;
        for (int o = 4; o; o >>= 1) s += __shfl_xor_sync(0xFFFFFFFFu, s, o);
        if (l == 0) sm[0] = s;
    }
    wcopy[(size_t)row * D_SZ + t] = v;
    g_w16[(size_t)row * D_SZ + t] = __float2half_rn(v);
    __syncthreads();
    if (t == 0) g_winv[row] = SCALAR / fmaxf(sqrtf(sm[0]), EPSV);
}

// ---------------------------------------------------------------------------
// 3) targets -> float
// ---------------------------------------------------------------------------
__global__ void targets_out_kernel(const int* __restrict__ tgt, float* __restrict__ dst) {
    int i = blockIdx.x * blockDim.x + threadIdx.x;
    if (i < B_SZ) dst[i] = (float)tgt[i];
}

// ---------------------------------------------------------------------------
// 4) sequential momentum update (exact batch order, duplicate-safe)
// ---------------------------------------------------------------------------
__global__ void seq_update_kernel(const int* __restrict__ tgt, float* __restrict__ wout) {
    int i = blockIdx.x;
    int t = threadIdx.x;
    int cls = tgt[i];
    __shared__ int first;
    __shared__ float sm[9];
    if (t == 0) first = 1;
    __syncthreads();
    for (int j = t; j < i; j += 256)
        if (tgt[j] == cls) first = 0;
    __syncthreads();
    if (!first) return;
    float v = wout[(size_t)cls * D_SZ + t];
    for (int j = i; j < B_SZ; ++j) {
        if (tgt[j] != cls) continue;
        v = MOM * v + (1.0f - MOM) * g_xnorm[j * D_SZ + t];
        float ss = v * v;
        for (int o = 16; o; o >>= 1) ss += __shfl_xor_sync(0xFFFFFFFFu, ss, o);
        int w = t >> 5, l = t & 31;
        if (l == 0) sm[w] = ss;
        __syncthreads();
        if (t == 0) {
            float s = 0.0f;
            for (int k = 0; k < 8; ++k) s += sm[k];
            sm[8] = s;
        }
        __syncthreads();
        v = v / fmaxf(sqrtf(sm[8]), EPSV);
        __syncthreads();
    }
    wout[(size_t)cls * D_SZ + t] = v;
}

// ---------------------------------------------------------------------------
// 5) fp16 single-product GEMM, CTA tile 128(M) x 256(N), 8 warps of 64x64.
//    k-chunk 32, 4-stage cp.async pipeline.
// ---------------------------------------------------------------------------
#define PITCH       80                        /* bytes per smem row (32 fp16 + pad) */
#define A_TILE      (128 * PITCH)             /* 10240 */
#define B_TILE      (256 * PITCH)             /* 20480 */
#define OFF_A       0
#define OFF_B       A_TILE
#define STAGE_BYTES (A_TILE + B_TILE)         /* 30720 */
#define NSTAGE      4
#define SMEM_GEMM   (NSTAGE * STAGE_BYTES)    /* 122880 */

__device__ __forceinline__ void load_chunk(uint32_t stage, int kc, int b0, int c0, int tid) {
    // A tile: 128 rows x 4 segs (16B each) = 512 segs -> 2 per thread
#pragma unroll
    for (int i = 0; i < 2; ++i) {
        int s = tid * 2 + i;
        int row = s >> 2, cs = s & 3;
        uint32_t so = (uint32_t)(row * PITCH + cs * 16);
        cpa16(stage + OFF_A + so, g_xh + (size_t)(b0 + row) * D_SZ + kc * 32 + cs * 8);
    }
    // B tile: 256 rows x 4 segs = 1024 segs -> 4 per thread
#pragma unroll
    for (int i = 0; i < 4; ++i) {
        int s = tid * 4 + i;
        int row = s >> 2, cs = s & 3;
        uint32_t so = (uint32_t)(row * PITCH + cs * 16);
        cpa16(stage + OFF_B + so, g_w16 + (size_t)(c0 + row) * D_SZ + kc * 32 + cs * 8);
    }
    CP_COMMIT();
}

__global__ void __launch_bounds__(256, 1) gemm_mma_kernel(float* __restrict__ out) {
    extern __shared__ char smem[];
    uint32_t sb = smem_u32(smem);
    __shared__ float sw_winv[256];

    int tid = threadIdx.x, lane = tid & 31, warp = tid >> 5;
    int warp_m = warp >> 2;        // 0..1  (64 rows)
    int warp_n = warp & 3;         // 0..3  (64 cols)
    int b0 = blockIdx.x * 128;
    int c0 = blockIdx.y * 256;

    sw_winv[tid] = g_winv[c0 + tid];

    float acc[4][8][4];
#pragma unroll
    for (int mi = 0; mi < 4; ++mi)
#pragma unroll
        for (int ni = 0; ni < 8; ++ni)
#pragma unroll
            for (int q = 0; q < 4; ++q) acc[mi][ni][q] = 0.0f;

    // lane-derived ldmatrix row offsets
    int arow = (lane & 7) + ((lane >> 3) & 1) * 8;
    int aseg = lane >> 4;                                   // 0/1 -> +16B
    uint32_t a_off = (uint32_t)((warp_m * 64 + arow) * PITCH + aseg * 16);
    int brow = (lane & 7) + (lane >> 4) * 8;
    int bseg = (lane >> 3) & 1;
    uint32_t b_off = (uint32_t)((warp_n * 64 + brow) * PITCH + bseg * 16);

    load_chunk(sb + 0 * STAGE_BYTES, 0, b0, c0, tid);
    load_chunk(sb + 1 * STAGE_BYTES, 1, b0, c0, tid);
    load_chunk(sb + 2 * STAGE_BYTES, 2, b0, c0, tid);
    load_chunk(sb + 3 * STAGE_BYTES, 3, b0, c0, tid);

#pragma unroll
    for (int kc = 0; kc < 8; ++kc) {
        if (kc <= 4)      { CP_WAIT(3); }
        else if (kc == 5) { CP_WAIT(2); }
        else if (kc == 6) { CP_WAIT(1); }
        else              { CP_WAIT(0); }
        __syncthreads();
        uint32_t st = sb + (uint32_t)(kc & 3) * STAGE_BYTES;

#pragma unroll
        for (int kk = 0; kk < 2; ++kk) {
            uint32_t koff = (uint32_t)(kk * 32);
            uint32_t af[4][4], bf[4][4];
#pragma unroll
            for (int mi = 0; mi < 4; ++mi)
                ldsm_x4(af[mi], st + OFF_A + a_off + mi * (16 * PITCH) + koff);
#pragma unroll
            for (int n2 = 0; n2 < 4; ++n2)
                ldsm_x4(bf[n2], st + OFF_B + b_off + n2 * (16 * PITCH) + koff);

#pragma unroll
            for (int mi = 0; mi < 4; ++mi)
#pragma unroll
                for (int ni = 0; ni < 8; ++ni) {
                    uint32_t bp[2] = { bf[ni >> 1][(ni & 1) * 2], bf[ni >> 1][(ni & 1) * 2 + 1] };
                    mma16816_f16(acc[mi][ni], af[mi], bp);
                }
        }
        __syncthreads();
        if (kc < 4) load_chunk(st, kc + 4, b0, c0, tid);
    }

    // epilogue: scale by winv, write predicts (guard C_SZ edge; stores 2-col aligned)
    int rbase = warp_m * 64 + (lane >> 2);
    int ncol2 = 2 * (lane & 3);
#pragma unroll
    for (int mi = 0; mi < 4; ++mi) {
#pragma unroll
        for (int ni = 0; ni < 8; ++ni) {
            int n_local = warp_n * 64 + ni * 8 + ncol2;
            int n_glob  = c0 + n_local;
            if (n_glob >= C_SZ) continue;
            float w0 = sw_winv[n_local], w1 = sw_winv[n_local + 1];
            int m0 = b0 + rbase + mi * 16;
            float2 v0 = make_float2(acc[mi][ni][0] * w0, acc[mi][ni][1] * w1);
            float2 v1 = make_float2(acc[mi][ni][2] * w0, acc[mi][ni][3] * w1);
            *(float2*)(out + (size_t)m0 * C_SZ + n_glob)       = v0;
            *(float2*)(out + (size_t)(m0 + 8) * C_SZ + n_glob) = v1;
        }
    }
}

// ---------------------------------------------------------------------------
extern "C" void kernel_launch(void* const* d_in, const int* in_sizes, int n_in,
                              void* d_out, int out_size) {
    const float* x   = (const float*)d_in[0];
    const int*   tgt = (const int*)d_in[1];
    const float* w   = (const float*)d_in[2];
    float* out = (float*)d_out;

    static bool attr_set = false;
    if (!attr_set) {
        cudaFuncSetAttribute(gemm_mma_kernel, cudaFuncAttributeMaxDynamicSharedMemorySize, SMEM_GEMM);
        attr_set = true;
    }

    normalize_x_kernel<<<B_SZ, 256>>>(x);
    prep_w_kernel<<<C_PAD, 256>>>(w, out + OUT_W);
    targets_out_kernel<<<(B_SZ + 255) / 256, 256>>>(tgt, out + OUT_TGT);
    seq_update_kernel<<<B_SZ, 256>>>(tgt, out + OUT_W);

    dim3 grid(B_SZ / 128, C_PAD / 256);   // (8, 391); x fastest -> CTAs sharing B tile run together
    gemm_mma_kernel<<<grid, 256, SMEM_GEMM>>>(out + OUT_PRED);
}

// round 14
// speedup vs baseline: 2.2230x; 1.3469x over previous
#include <cuda_runtime.h>
#include <cuda_bf16.h>
#include <cuda_fp16.h>
#include <math.h>
#include <stdint.h>

#define B_SZ   1024
#define C_SZ   100000
#define C_PAD  100096          /* 782 * 128 */
#define D_SZ   256
#define EPSV   1e-12f
#define SCALAR 30.0f
#define MOM    0.5f

// out layout: predicts | targets(as float) | new_weight
#define OUT_PRED 0
#define OUT_TGT  (B_SZ * C_SZ)
#define OUT_W    (B_SZ * C_SZ + B_SZ)

// ---------------- scratch (static device globals; no allocs) ----------------
__device__ float g_xnorm[B_SZ * D_SZ];
__device__ float g_winv[C_PAD];
__device__ __align__(16) __half g_xh[B_SZ * D_SZ];
__device__ __align__(16) __half g_w16[(size_t)C_PAD * D_SZ];

// ---------------- PTX helpers (portable: sm_80+ instructions only) ----------
__device__ __forceinline__ uint32_t smem_u32(const void* p) {
    uint32_t a;
    asm("{ .reg .u64 t; cvta.to.shared.u64 t, %1; cvt.u32.u64 %0, t; }" : "=r"(a) : "l"(p));
    return a;
}
__device__ __forceinline__ void cpa16(uint32_t dst, const void* src) {
    asm volatile("cp.async.cg.shared.global [%0], [%1], 16;"
        :: "r"(dst), "l"((unsigned long long)__cvta_generic_to_global(src)) : "memory");
}
#define CP_COMMIT() asm volatile("cp.async.commit_group;" ::: "memory")
#define CP_WAIT(n)  asm volatile("cp.async.wait_group %0;" :: "n"(n) : "memory")

__device__ __forceinline__ void ldsm_x4(uint32_t* r, uint32_t addr) {
    asm volatile("ldmatrix.sync.aligned.m8n8.x4.shared.b16 {%0,%1,%2,%3}, [%4];"
        : "=r"(r[0]), "=r"(r[1]), "=r"(r[2]), "=r"(r[3]) : "r"(addr));
}
__device__ __forceinline__ void mma16816_f16(float* c, const uint32_t* a, const uint32_t* b) {
    asm volatile("mma.sync.aligned.m16n8k16.row.col.f32.f16.f16.f32 "
        "{%0,%1,%2,%3}, {%4,%5,%6,%7}, {%8,%9}, {%0,%1,%2,%3};"
        : "+f"(c[0]), "+f"(c[1]), "+f"(c[2]), "+f"(c[3])
        : "r"(a[0]), "r"(a[1]), "r"(a[2]), "r"(a[3]), "r"(b[0]), "r"(b[1]));
}

// ---------------------------------------------------------------------------
// 1) normalize inputs (fp32 for seq_update) + emit fp16
// ---------------------------------------------------------------------------
__global__ void normalize_x_kernel(const float* __restrict__ x) {
    int b = blockIdx.x;
    int t = threadIdx.x;
    float v = x[b * D_SZ + t];
    float ss = v * v;
    __shared__ float sm[8];
    for (int o = 16; o; o >>= 1) ss += __shfl_xor_sync(0xFFFFFFFFu, ss, o);
    int w = t >> 5, l = t & 31;
    if (l == 0) sm[w] = ss;
    __syncthreads();
    if (w == 0) {
        float s = (l < 8) ? sm[l] : 0.0f;
        for (int o = 4; o; o >>= 1) s += __shfl_xor_sync(0xFFFFFFFFu, s, o);
        if (l == 0) sm[0] = s;
    }
    __syncthreads();
    float nrm = sqrtf(sm[0]);
    float xn = v / fmaxf(nrm, EPSV);
    g_xnorm[b * D_SZ + t] = xn;
    g_xh[b * D_SZ + t] = __float2half_rn(xn);
}

// ---------------------------------------------------------------------------
// 2) fused weight prep, warp-per-row (8 rows/block): one read of w produces
//    fp32 copy, fp16 conversion, and winv. Padded rows zeroed.
// ---------------------------------------------------------------------------
__global__ void prep_w_kernel(const float* __restrict__ w, float* __restrict__ wcopy) {
    int row = blockIdx.x * 8 + (threadIdx.x >> 5);
    int lane = threadIdx.x & 31;
    if (row >= C_PAD) return;
    size_t base = (size_t)row * D_SZ + lane * 8;
    if (row >= C_SZ) {
        __half z[8];
#pragma unroll
        for (int k = 0; k < 8; ++k) z[k] = __float2half_rn(0.0f);
        *(uint4*)(g_w16 + base) = *(uint4*)z;
        if (lane == 0) g_winv[row] = 0.0f;
        return;
    }
    float4 a = *(const float4*)(w + base);
    float4 b = *(const float4*)(w + base + 4);
    float ss = a.x*a.x + a.y*a.y + a.z*a.z + a.w*a.w
             + b.x*b.x + b.y*b.y + b.z*b.z + b.w*b.w;
    for (int o = 16; o; o >>= 1) ss += __shfl_xor_sync(0xFFFFFFFFu, ss, o);
    // fp32 copy
    *(float4*)(wcopy + base)     = a;
    *(float4*)(wcopy + base + 4) = b;
    // fp16 convert
    __half h[8];
    h[0] = __float2half_rn(a.x); h[1] = __float2half_rn(a.y);
    h[2] = __float2half_rn(a.z); h[3] = __float2half_rn(a.w);
    h[4] = __float2half_rn(b.x); h[5] = __float2half_rn(b.y);
    h[6] = __float2half_rn(b.z); h[7] = __float2half_rn(b.w);
    *(uint4*)(g_w16 + base) = *(uint4*)h;
    if (lane == 0) g_winv[row] = SCALAR / fmaxf(sqrtf(ss), EPSV);
}

// ---------------------------------------------------------------------------
// 3) targets -> float
// ---------------------------------------------------------------------------
__global__ void targets_out_kernel(const int* __restrict__ tgt, float* __restrict__ dst) {
    int i = blockIdx.x * blockDim.x + threadIdx.x;
    if (i < B_SZ) dst[i] = (float)tgt[i];
}

// ---------------------------------------------------------------------------
// 4) sequential momentum update (exact batch order, duplicate-safe).
//    Targets cached in shared memory: kills the global pointer-chase.
// ---------------------------------------------------------------------------
__global__ void seq_update_kernel(const int* __restrict__ tgt, float* __restrict__ wout) {
    int i = blockIdx.x;
    int t = threadIdx.x;
    __shared__ int stgt[B_SZ];
    __shared__ int first;
    __shared__ float sm[9];
    for (int j = t; j < B_SZ; j += 256) stgt[j] = tgt[j];
    if (t == 0) first = 1;
    __syncthreads();
    int cls = stgt[i];
    for (int j = t; j < i; j += 256)
        if (stgt[j] == cls) first = 0;
    __syncthreads();
    if (!first) return;
    float v = wout[(size_t)cls * D_SZ + t];
    for (int j = i; j < B_SZ; ++j) {
        if (stgt[j] != cls) continue;
        v = MOM * v + (1.0f - MOM) * g_xnorm[j * D_SZ + t];
        float ss = v * v;
        for (int o = 16; o; o >>= 1) ss += __shfl_xor_sync(0xFFFFFFFFu, ss, o);
        int w = t >> 5, l = t & 31;
        if (l == 0) sm[w] = ss;
        __syncthreads();
        if (t == 0) {
            float s = 0.0f;
            for (int k = 0; k < 8; ++k) s += sm[k];
            sm[8] = s;
        }
        __syncthreads();
        v = v / fmaxf(sqrtf(sm[8]), EPSV);
        __syncthreads();
    }
    wout[(size_t)cls * D_SZ + t] = v;
}

// ---------------------------------------------------------------------------
// 5) fp16 GEMM, CTA tile 128(M) x 128(N), 8 warps of 32x64, 2 CTAs/SM.
//    k-chunk 32, 4-stage cp.async pipeline.
// ---------------------------------------------------------------------------
#define PITCH       80                        /* bytes per smem row (32 fp16 + pad) */
#define A_TILE      (128 * PITCH)             /* 10240 */
#define B_TILE      (128 * PITCH)             /* 10240 */
#define OFF_A       0
#define OFF_B       A_TILE
#define STAGE_BYTES (A_TILE + B_TILE)         /* 20480 */
#define NSTAGE      4
#define SMEM_GEMM   (NSTAGE * STAGE_BYTES)    /* 81920; x2 CTAs = 163840 < 228KB */

__device__ __forceinline__ void load_chunk(uint32_t stage, int kc, int b0, int c0, int tid) {
    // A tile: 128 rows x 4 segs (16B each) = 512 segs -> 2 per thread
#pragma unroll
    for (int i = 0; i < 2; ++i) {
        int s = tid * 2 + i;
        int row = s >> 2, cs = s & 3;
        uint32_t so = (uint32_t)(row * PITCH + cs * 16);
        cpa16(stage + OFF_A + so, g_xh + (size_t)(b0 + row) * D_SZ + kc * 32 + cs * 8);
    }
    // B tile: 128 rows x 4 segs = 512 segs -> 2 per thread
#pragma unroll
    for (int i = 0; i < 2; ++i) {
        int s = tid * 2 + i;
        int row = s >> 2, cs = s & 3;
        uint32_t so = (uint32_t)(row * PITCH + cs * 16);
        cpa16(stage + OFF_B + so, g_w16 + (size_t)(c0 + row) * D_SZ + kc * 32 + cs * 8);
    }
    CP_COMMIT();
}

__global__ void __launch_bounds__(256, 2) gemm_mma_kernel(float* __restrict__ out) {
    extern __shared__ char smem[];
    uint32_t sb = smem_u32(smem);
    __shared__ float sw_winv[128];

    int tid = threadIdx.x, lane = tid & 31, warp = tid >> 5;
    int warp_m = warp >> 1;        // 0..3  (32 rows each)
    int warp_n = warp & 1;         // 0..1  (64 cols each)
    int b0 = blockIdx.x * 128;
    int c0 = blockIdx.y * 128;

    if (tid < 128) sw_winv[tid] = g_winv[c0 + tid];

    float acc[2][8][4];
#pragma unroll
    for (int mi = 0; mi < 2; ++mi)
#pragma unroll
        for (int ni = 0; ni < 8; ++ni)
#pragma unroll
            for (int q = 0; q < 4; ++q) acc[mi][ni][q] = 0.0f;

    // lane-derived ldmatrix row offsets
    int arow = (lane & 7) + ((lane >> 3) & 1) * 8;
    int aseg = lane >> 4;                                   // 0/1 -> +16B
    uint32_t a_off = (uint32_t)((warp_m * 32 + arow) * PITCH + aseg * 16);
    int brow = (lane & 7) + (lane >> 4) * 8;
    int bseg = (lane >> 3) & 1;
    uint32_t b_off = (uint32_t)((warp_n * 64 + brow) * PITCH + bseg * 16);

    load_chunk(sb + 0 * STAGE_BYTES, 0, b0, c0, tid);
    load_chunk(sb + 1 * STAGE_BYTES, 1, b0, c0, tid);
    load_chunk(sb + 2 * STAGE_BYTES, 2, b0, c0, tid);
    load_chunk(sb + 3 * STAGE_BYTES, 3, b0, c0, tid);

#pragma unroll
    for (int kc = 0; kc < 8; ++kc) {
        if (kc <= 4)      { CP_WAIT(3); }
        else if (kc == 5) { CP_WAIT(2); }
        else if (kc == 6) { CP_WAIT(1); }
        else              { CP_WAIT(0); }
        __syncthreads();
        uint32_t st = sb + (uint32_t)(kc & 3) * STAGE_BYTES;

#pragma unroll
        for (int kk = 0; kk < 2; ++kk) {
            uint32_t koff = (uint32_t)(kk * 32);
            uint32_t af[2][4], bf[4][4];
#pragma unroll
            for (int mi = 0; mi < 2; ++mi)
                ldsm_x4(af[mi], st + OFF_A + a_off + mi * (16 * PITCH) + koff);
#pragma unroll
            for (int n2 = 0; n2 < 4; ++n2)
                ldsm_x4(bf[n2], st + OFF_B + b_off + n2 * (16 * PITCH) + koff);

#pragma unroll
            for (int mi = 0; mi < 2; ++mi)
#pragma unroll
                for (int ni = 0; ni < 8; ++ni) {
                    uint32_t bp[2] = { bf[ni >> 1][(ni & 1) * 2], bf[ni >> 1][(ni & 1) * 2 + 1] };
                    mma16816_f16(acc[mi][ni], af[mi], bp);
                }
        }
        __syncthreads();
        if (kc < 4) load_chunk(st, kc + 4, b0, c0, tid);
    }

    // epilogue: scale by winv, write predicts (guard C_SZ edge; stores 2-col aligned)
    int rbase = warp_m * 32 + (lane >> 2);
    int ncol2 = 2 * (lane & 3);
#pragma unroll
    for (int mi = 0; mi < 2; ++mi) {
#pragma unroll
        for (int ni = 0; ni < 8; ++ni) {
            int n_local = warp_n * 64 + ni * 8 + ncol2;
            int n_glob  = c0 + n_local;
            if (n_glob >= C_SZ) continue;
            float w0 = sw_winv[n_local], w1 = sw_winv[n_local + 1];
            int m0 = b0 + rbase + mi * 16;
            float2 v0 = make_float2(acc[mi][ni][0] * w0, acc[mi][ni][1] * w1);
            float2 v1 = make_float2(acc[mi][ni][2] * w0, acc[mi][ni][3] * w1);
            *(float2*)(out + (size_t)m0 * C_SZ + n_glob)       = v0;
            *(float2*)(out + (size_t)(m0 + 8) * C_SZ + n_glob) = v1;
        }
    }
}

// ---------------------------------------------------------------------------
extern "C" void kernel_launch(void* const* d_in, const int* in_sizes, int n_in,
                              void* d_out, int out_size) {
    const float* x   = (const float*)d_in[0];
    const int*   tgt = (const int*)d_in[1];
    const float* w   = (const float*)d_in[2];
    float* out = (float*)d_out;

    static bool attr_set = false;
    if (!attr_set) {
        cudaFuncSetAttribute(gemm_mma_kernel, cudaFuncAttributeMaxDynamicSharedMemorySize, SMEM_GEMM);
        attr_set = true;
    }

    normalize_x_kernel<<<B_SZ, 256>>>(x);
    prep_w_kernel<<<C_PAD / 8, 256>>>(w, out + OUT_W);
    targets_out_kernel<<<(B_SZ + 255) / 256, 256>>>(tgt, out + OUT_TGT);
    seq_update_kernel<<<B_SZ, 256>>>(tgt, out + OUT_W);

    dim3 grid(B_SZ / 128, C_PAD / 128);   // (8, 782); x fastest -> CTAs sharing B tile run together
    gemm_mma_kernel<<<grid, 256, SMEM_GEMM>>>(out + OUT_PRED);
}